// round 15
// baseline (speedup 1.0000x reference)
#include <cuda_runtime.h>

#define BN_EPS 1e-5f

// ---------------- f32x2 packed-math helpers ----------------
typedef unsigned long long u64t;

__device__ __forceinline__ u64t pk2(float lo, float hi) {
  u64t r;
  asm("mov.b64 %0, {%1, %2};" : "=l"(r)
      : "r"(__float_as_uint(lo)), "r"(__float_as_uint(hi)));
  return r;
}
__device__ __forceinline__ void fma2(u64t& d, u64t a, u64t b) {
  asm("fma.rn.f32x2 %0, %1, %2, %0;" : "+l"(d) : "l"(a), "l"(b));
}
__device__ __forceinline__ float2 upk2(u64t v) {
  unsigned lo, hi;
  asm("mov.b64 {%0, %1}, %2;" : "=r"(lo), "=r"(hi) : "l"(v));
  return make_float2(__uint_as_float(lo), __uint_as_float(hi));
}

// ---------------- scratch (device globals; no allocation allowed) ----------------
__device__ float g_A[33554432];  // 128MB: h1 [32,16,256,256] and d2 [32,16,256,256]
__device__ float g_B[8388608];   //  32MB: h2 [32,16,128,128] and d1 [32,16,128,128]
__device__ float g_C[524288];    //   2MB: h3 [32,4,64,64]
__device__ float g_P[524288];    //   2MB: post-conv [32,4,64,64]
__device__ float g_stats[136];   // [0:68) per-channel sums, [68:136) sumsqs
__device__ float g_loss[2];      // [0]=vq sq-dist sum, [1]=recon sq-err sum

// stat-set channel offsets: bn1=0(16) bn2=16(16) bn3=32(4) bn4=36(16) bn5=52(16)

__global__ void k_zero() {
  int t = threadIdx.x;
  if (t < 136) g_stats[t] = 0.f;
  if (t < 2)   g_loss[t]  = 0.f;
}

// inline BN finalize: per-block compute of scale/shift from stats
template <int CIN>
__device__ __forceinline__ void bn_inline(float* ssc, float* ssh, int in_off,
                                          const float* __restrict__ bng,
                                          const float* __restrict__ bnb, float binv) {
  int c = threadIdx.x;
  if (c < CIN) {
    float mean = g_stats[in_off + c] * binv;
    float var  = g_stats[68 + in_off + c] * binv - mean * mean;
    float s = bng[c] * rsqrtf(var + BN_EPS);
    ssc[c] = s;
    ssh[c] = bnb[c] - mean * s;
  }
}

// block-level per-channel sum/sumsq reduction -> global atomics (NW warps/block)
template <int NCH, int NW>
__device__ __forceinline__ void stats_reduce(float* ssum, float* ssq, int off) {
#pragma unroll
  for (int q = 0; q < NCH; q++) {
    float a = ssum[q], b = ssq[q];
#pragma unroll
    for (int o = 16; o > 0; o >>= 1) {
      a += __shfl_xor_sync(0xffffffffu, a, o);
      b += __shfl_xor_sync(0xffffffffu, b, o);
    }
    ssum[q] = a; ssq[q] = b;
  }
  __shared__ float red[2][NW][NCH];
  int lane = threadIdx.x & 31, w = threadIdx.x >> 5;
  if (lane == 0) {
#pragma unroll
    for (int q = 0; q < NCH; q++) { red[0][w][q] = ssum[q]; red[1][w][q] = ssq[q]; }
  }
  __syncthreads();
  if (threadIdx.x < NCH) {
    float a = 0.f, b = 0.f;
#pragma unroll
    for (int ww = 0; ww < NW; ww++) { a += red[0][ww][threadIdx.x]; b += red[1][ww][threadIdx.x]; }
    atomicAdd(&g_stats[off + threadIdx.x], a);
    atomicAdd(&g_stats[68 + off + threadIdx.x], b);
  }
}

// ---------------- conv k=4 s=2 p=1 ----------------
// Thread: PX consecutive ox, COUT/NSPLIT output channels (oc-paired f32x2), one (b,oy).
// NSPLIT>1: block-uniform oc split (keeps PX-per-weight reuse; halves acc regs ->
// 3 blocks/SM). Per (ky,ic): row loaded once (float4 interior path); PAD IS ZERO.
template <int CIN, int COUT, int HOUT, int WOUT, int IN_OFF, int OUT_OFF, int PX, int BD,
          int NSPLIT>
__global__ void __launch_bounds__(BD, (BD == 128) ? 5 : ((NSPLIT > 1) ? 3 : 2))
k_conv(const float* __restrict__ in, const float* __restrict__ wgt,
       const float* __restrict__ bias, float* __restrict__ out,
       const float* __restrict__ bng, const float* __restrict__ bnb, float binv) {
  constexpr int HIN = 2 * HOUT, WIN = 2 * WOUT;
  constexpr int COUT_T = COUT / NSPLIT;
  constexpr int NJ = COUT_T / 2;
  constexpr int NV = 2 * PX + 2;
  __shared__ __align__(16) float sw[16 * CIN * COUT_T];
  __shared__ float ssc[CIN], ssh[CIN];

  int nblk   = gridDim.x / NSPLIT;
  int split  = (NSPLIT > 1) ? (blockIdx.x / nblk) : 0;
  int bblk   = blockIdx.x - split * nblk;
  int ocbase = split * COUT_T;

  for (int i = threadIdx.x; i < 16 * CIN * COUT_T; i += blockDim.x) {
    int tap = i / (CIN * COUT_T);
    int r = i - tap * CIN * COUT_T;
    int ic = r / COUT_T, oc = r - ic * COUT_T;
    sw[i] = wgt[((ocbase + oc) * CIN + ic) * 16 + tap];
  }
  if (IN_OFF >= 0) bn_inline<CIN>(ssc, ssh, IN_OFF, bng, bnb, binv);
  __syncthreads();

  int gtid = bblk * blockDim.x + threadIdx.x;
  int base = gtid * PX;
  int ox0 = base % WOUT;  // multiple of PX
  int t2  = base / WOUT;
  int oy  = t2 % HOUT;
  int b   = t2 / HOUT;

  int ox2 = 2 * ox0 - 1;  // vr[m] = in_row[ox2 + m], m = 0..NV-1
  bool interior = (ox0 > 0) && (ox0 < WOUT - PX);

  u64t acc2[PX][NJ];
#pragma unroll
  for (int j = 0; j < NJ; j++) {
    u64t bb = pk2(bias[ocbase + 2 * j], bias[ocbase + 2 * j + 1]);
#pragma unroll
    for (int p = 0; p < PX; p++) acc2[p][j] = bb;
  }

#pragma unroll 1
  for (int ky = 0; ky < 4; ky++) {
    int iy = 2 * oy - 1 + ky;
    if ((unsigned)iy >= (unsigned)HIN) continue;
#pragma unroll 1
    for (int ic = 0; ic < CIN; ic++) {
      int rowoff = ((b * CIN + ic) * HIN + iy) * WIN;
      float vr[NV];
      if (interior) {
        const float4* r4 = (const float4*)(in + rowoff + 2 * ox0 - 4);  // 16B aligned
        float4 a = r4[0], c = r4[1];
        vr[0] = a.w;
        vr[1] = c.x; vr[2] = c.y; vr[3] = c.z; vr[4] = c.w;
        if (PX == 2) {
          vr[5] = in[rowoff + 2 * ox0 + 4];
        } else {
          float4 d = r4[2];
          vr[5] = d.x; vr[6] = d.y; vr[7] = d.z; vr[8] = d.w;
          vr[9] = in[rowoff + 2 * ox0 + 8];
        }
        if (IN_OFF >= 0) {
          float sc = ssc[ic], sh = ssh[ic];
#pragma unroll
          for (int m = 0; m < NV; m++) vr[m] = fmaxf(fmaf(vr[m], sc, sh), 0.f);
        }
      } else {
        float sc = (IN_OFF >= 0) ? ssc[ic] : 0.f;
        float sh = (IN_OFF >= 0) ? ssh[ic] : 0.f;
#pragma unroll
        for (int m = 0; m < NV; m++) {
          int ix = ox2 + m;
          float t = 0.f;
          if ((unsigned)ix < (unsigned)WIN) {
            t = in[rowoff + ix];
            if (IN_OFF >= 0) t = fmaxf(fmaf(t, sc, sh), 0.f);
          }
          vr[m] = t;  // pad stays exactly 0
        }
      }

      u64t vv[NV];
#pragma unroll
      for (int m = 0; m < NV; m++) vv[m] = pk2(vr[m], vr[m]);

      const u64t* wtap = (const u64t*)&sw[(ky * 4 * CIN + ic) * COUT_T];
#pragma unroll
      for (int kx = 0; kx < 4; kx++) {
        const u64t* wrow2 = wtap + kx * (CIN * NJ);
#pragma unroll
        for (int j = 0; j < NJ; j++) {
          u64t w2 = wrow2[j];
#pragma unroll
          for (int p = 0; p < PX; p++) fma2(acc2[p][j], vv[kx + 2 * p], w2);
        }
      }
    }
  }

  float ssum[COUT_T], ssq[COUT_T];
#pragma unroll
  for (int j = 0; j < NJ; j++) {
    int ocl = 2 * j;
    int ocg = ocbase + ocl;
    float oa[PX], ob[PX];
#pragma unroll
    for (int p = 0; p < PX; p++) {
      float2 pr = upk2(acc2[p][j]);
      oa[p] = pr.x; ob[p] = pr.y;
    }
    if (PX == 4) {
      *(float4*)&out[((b * COUT + ocg) * HOUT + oy) * WOUT + ox0] =
          make_float4(oa[0], oa[1], oa[2], oa[3]);
      *(float4*)&out[((b * COUT + ocg + 1) * HOUT + oy) * WOUT + ox0] =
          make_float4(ob[0], ob[1], ob[2], ob[3]);
    } else {
      *(float2*)&out[((b * COUT + ocg) * HOUT + oy) * WOUT + ox0] =
          make_float2(oa[0], oa[1]);
      *(float2*)&out[((b * COUT + ocg + 1) * HOUT + oy) * WOUT + ox0] =
          make_float2(ob[0], ob[1]);
    }
    float sa = 0.f, qa = 0.f, sb = 0.f, qb = 0.f;
#pragma unroll
    for (int p = 0; p < PX; p++) {
      sa += oa[p]; qa += oa[p] * oa[p];
      sb += ob[p]; qb += ob[p] * ob[p];
    }
    ssum[ocl] = sa; ssq[ocl] = qa;
    ssum[ocl + 1] = sb; ssq[ocl + 1] = qb;
  }
  stats_reduce<COUT_T, BD / 32>(ssum, ssq, OUT_OFF + ocbase);
}

// ---------------- conv-transpose k=4 s=2 p=1 (r14 version) ----------------
template <int CIN, int COUT, int HOUT, int WOUT, int IN_OFF, int OUT_OFF>
__global__ void __launch_bounds__(256, 2)
k_deconv(const float* __restrict__ in, const float* __restrict__ wgt,
         const float* __restrict__ bias, float* __restrict__ out,
         const float* __restrict__ bng, const float* __restrict__ bnb, float binv) {
  constexpr int HIN = HOUT / 2, WIN = WOUT / 2;
  constexpr int NJ = COUT / 2;
  __shared__ __align__(16) float sw[16 * CIN * COUT];
  __shared__ float ssc[CIN], ssh[CIN];
  for (int i = threadIdx.x; i < 16 * CIN * COUT; i += blockDim.x) {
    int tap = i / (CIN * COUT);
    int r = i - tap * CIN * COUT;
    int ic = r / COUT, oc = r - ic * COUT;
    sw[i] = wgt[(ic * COUT + oc) * 16 + tap];
  }
  if (IN_OFF >= 0) bn_inline<CIN>(ssc, ssh, IN_OFF, bng, bnb, binv);
  __syncthreads();

  int gtid = blockIdx.x * blockDim.x + threadIdx.x;
  int base = gtid * 4;
  int ox0 = base % WOUT;  // multiple of 4
  int t2  = base / WOUT;
  int oy  = t2 % HOUT;
  int b   = t2 / HOUT;

  int ry  = (oy + 1) & 1;        // valid ky in {ry, ry+2}
  int iy0 = (oy + 1 - ry) >> 1;  // iy for ky=ry; ky=ry+2 -> iy0-1
  int ixb = (ox0 >> 1) - 1;      // vr[m] = row[ixb+m], m 0..3

  u64t acc2[4][NJ];
#pragma unroll
  for (int j = 0; j < NJ; j++) {
    u64t bb = pk2(bias[2 * j], bias[2 * j + 1]);
#pragma unroll
    for (int p = 0; p < 4; p++) acc2[p][j] = bb;
  }

#pragma unroll 1
  for (int ty = 0; ty < 2; ty++) {
    int iy = iy0 - ty;
    if ((unsigned)iy >= (unsigned)HIN) continue;
    int ky = ry + 2 * ty;
#pragma unroll 2
    for (int ic = 0; ic < CIN; ic++) {
      int rowoff = ((b * CIN + ic) * HIN + iy) * WIN;
      float sc = (IN_OFF >= 0) ? ssc[ic] : 0.f;
      float sh = (IN_OFF >= 0) ? ssh[ic] : 0.f;
      float vr[4];
#pragma unroll
      for (int m = 0; m < 4; m++) {
        int ix = ixb + m;
        float t = 0.f;
        if ((unsigned)ix < (unsigned)WIN) {
          t = in[rowoff + ix];
          if (IN_OFF >= 0) t = fmaxf(fmaf(t, sc, sh), 0.f);
        }
        vr[m] = t;  // pad stays exactly 0
      }
      u64t vv[4];
#pragma unroll
      for (int m = 0; m < 4; m++) vv[m] = pk2(vr[m], vr[m]);

#pragma unroll
      for (int pc = 0; pc < 2; pc++) {
        int rx = (pc + 1) & 1;
#pragma unroll
        for (int tx = 0; tx < 2; tx++) {
          int kx = rx + 2 * tx;
          int m0 = pc + 1 - tx;  // pixel pc; pixel pc+2 uses m0+1
          const u64t* wrow2 = (const u64t*)&sw[((ky * 4 + kx) * CIN + ic) * COUT];
#pragma unroll
          for (int j = 0; j < NJ; j++) {
            u64t w2 = wrow2[j];
            fma2(acc2[pc][j],     vv[m0],     w2);
            fma2(acc2[pc + 2][j], vv[m0 + 1], w2);
          }
        }
      }
    }
  }

  float ssum[COUT], ssq[COUT];
#pragma unroll
  for (int j = 0; j < NJ; j++) {
    float2 p0 = upk2(acc2[0][j]), p1 = upk2(acc2[1][j]);
    float2 p2 = upk2(acc2[2][j]), p3 = upk2(acc2[3][j]);
    float4 oa = make_float4(p0.x, p1.x, p2.x, p3.x);
    float4 ob = make_float4(p0.y, p1.y, p2.y, p3.y);
    int oc0 = 2 * j;
    *(float4*)&out[((b * COUT + oc0) * HOUT + oy) * WOUT + ox0] = oa;
    *(float4*)&out[((b * COUT + oc0 + 1) * HOUT + oy) * WOUT + ox0] = ob;
    ssum[oc0]     = oa.x + oa.y + oa.z + oa.w;
    ssq[oc0]      = oa.x * oa.x + oa.y * oa.y + oa.z * oa.z + oa.w * oa.w;
    ssum[oc0 + 1] = ob.x + ob.y + ob.z + ob.w;
    ssq[oc0 + 1]  = ob.x * ob.x + ob.y * ob.y + ob.z * ob.z + ob.w * ob.w;
  }
  stats_reduce<COUT, 8>(ssum, ssq, OUT_OFF);
}

// ---------------- fused: bn3+relu -> 1x1 pre-conv -> VQ -> 1x1 post-conv ----------------
__global__ void k_vq(const float* __restrict__ C, const float* __restrict__ wpre,
                     const float* __restrict__ bpre, const float* __restrict__ cb,
                     const float* __restrict__ wpost, const float* __restrict__ bpost,
                     const float* __restrict__ g3, const float* __restrict__ be3) {
  __shared__ float scb[512];
  __shared__ float ssc[4], ssh[4];
  for (int i = threadIdx.x; i < 512; i += blockDim.x) scb[i] = cb[i];
  bn_inline<4>(ssc, ssh, 32, g3, be3, 1.f / 131072.f);
  __syncthreads();

  int t  = blockIdx.x * blockDim.x + threadIdx.x;  // 131072 pixels
  int sp = t & 4095;
  int b  = t >> 12;

  float h[4];
#pragma unroll
  for (int ic = 0; ic < 4; ic++) {
    float raw = C[((b * 4 + ic) << 12) + sp];
    h[ic] = fmaxf(fmaf(raw, ssc[ic], ssh[ic]), 0.f);
  }
  float q0 = bpre[0], q1 = bpre[1];
#pragma unroll
  for (int ic = 0; ic < 4; ic++) {
    q0 = fmaf(h[ic], wpre[ic], q0);
    q1 = fmaf(h[ic], wpre[4 + ic], q1);
  }

  float best = 3.4e38f;
  int bi = 0;
  const float2* cb2 = (const float2*)scb;
#pragma unroll 8
  for (int j = 0; j < 256; j++) {
    float2 c = cb2[j];
    float d0 = q0 - c.x, d1 = q1 - c.y;
    float d = d0 * d0 + d1 * d1;
    if (d < best) { best = d; bi = j; }  // first-min tie-break == jnp.argmin
  }
  float c0 = scb[2 * bi], c1 = scb[2 * bi + 1];

#pragma unroll
  for (int j = 0; j < 4; j++) {
    float pv = bpost[j] + wpost[2 * j] * c0 + wpost[2 * j + 1] * c1;
    g_P[((b * 4 + j) << 12) + sp] = pv;
  }

  float part = best;
#pragma unroll
  for (int o = 16; o > 0; o >>= 1) part += __shfl_xor_sync(0xffffffffu, part, o);
  __shared__ float red[8];
  int lane = threadIdx.x & 31, w = threadIdx.x >> 5;
  if (lane == 0) red[w] = part;
  __syncthreads();
  if (threadIdx.x == 0) {
    float a = 0.f;
#pragma unroll
    for (int ww = 0; ww < 8; ww++) a += red[ww];
    atomicAdd(&g_loss[0], a);
  }
}

// ---------------- final deconv (16->1) + sigmoid + recon loss (r14 version) ----------------
__global__ void __launch_bounds__(256, 2)
k_deconv3(const float* __restrict__ in, const float* __restrict__ wgt,
          const float* __restrict__ bias, const float* __restrict__ x,
          float* __restrict__ out,
          const float* __restrict__ g5, const float* __restrict__ be5) {
  constexpr int CIN = 16, HIN = 256, WIN = 256;
  __shared__ __align__(16) u64t swd[256];  // swd[tap*16+ic] = {w, w}
  __shared__ float ssc[16], ssh[16];
  if (threadIdx.x < 256) {
    int tap = threadIdx.x >> 4, ic = threadIdx.x & 15;
    float w = wgt[ic * 16 + tap];
    swd[threadIdx.x] = pk2(w, w);
  }
  bn_inline<16>(ssc, ssh, 52, g5, be5, 1.f / 2097152.f);
  __syncthreads();

  int gtid = blockIdx.x * blockDim.x + threadIdx.x;
  int base = gtid * 8;
  int ox0 = base & 511;
  int t2  = base >> 9;
  int oy  = t2 & 511;
  int b   = t2 >> 9;

  int ry  = (oy + 1) & 1;
  int iy0 = (oy + 1 - ry) >> 1;
  int ixb = (ox0 >> 1) - 1;  // vr[m] = row[ixb+m], m 0..5
  bool interior = (ox0 > 0) && (ox0 < 504);

  float bb = bias[0];
  u64t acc2[4];
#pragma unroll
  for (int s = 0; s < 4; s++) acc2[s] = pk2(bb, bb);

#pragma unroll 1
  for (int ty = 0; ty < 2; ty++) {
    int iy = iy0 - ty;
    if ((unsigned)iy >= (unsigned)HIN) continue;
    int ky = ry + 2 * ty;
#pragma unroll 1
    for (int ic = 0; ic < CIN; ic++) {
      int rowoff = ((b * CIN + ic) * HIN + iy) * WIN;
      float sc = ssc[ic], sh = ssh[ic];
      float vr[6];
      if (interior) {
        // ixb+1 = ox0/2, multiple of 4 -> 16B-aligned float4 covers vr[1..4]
        float v0 = in[rowoff + ixb];
        float4 c4 = *(const float4*)(in + rowoff + ixb + 1);
        float v5 = in[rowoff + ixb + 5];
        vr[0] = fmaxf(fmaf(v0,   sc, sh), 0.f);
        vr[1] = fmaxf(fmaf(c4.x, sc, sh), 0.f);
        vr[2] = fmaxf(fmaf(c4.y, sc, sh), 0.f);
        vr[3] = fmaxf(fmaf(c4.z, sc, sh), 0.f);
        vr[4] = fmaxf(fmaf(c4.w, sc, sh), 0.f);
        vr[5] = fmaxf(fmaf(v5,   sc, sh), 0.f);
      } else {
#pragma unroll
        for (int m = 0; m < 6; m++) {
          int ix = ixb + m;
          float t = 0.f;
          if ((unsigned)ix < (unsigned)WIN)
            t = fmaxf(fmaf(in[rowoff + ix], sc, sh), 0.f);
          vr[m] = t;  // pad stays exactly 0
        }
      }
      u64t vp[4];
#pragma unroll
      for (int m = 0; m < 4; m++) vp[m] = pk2(vr[m], vr[m + 2]);

#pragma unroll
      for (int pc = 0; pc < 2; pc++) {
        int rx = (pc + 1) & 1;
#pragma unroll
        for (int tx = 0; tx < 2; tx++) {
          int kx = rx + 2 * tx;
          u64t wd = swd[(ky * 4 + kx) * 16 + ic];
          int m0 = pc + 1 - tx;
          fma2(acc2[pc],     vp[m0],     wd);
          fma2(acc2[pc + 2], vp[m0 + 1], wd);
        }
      }
    }
  }

  float o[8];
#pragma unroll
  for (int s = 0; s < 4; s++) {
    float2 pr = upk2(acc2[s]);
    o[s]     = 1.f / (1.f + __expf(-pr.x));
    o[s + 4] = 1.f / (1.f + __expf(-pr.y));
  }

  int obase = (b * 512 + oy) * 512 + ox0;
  float4 xa = *(const float4*)&x[obase];
  float4 xb = *(const float4*)&x[obase + 4];
  *(float4*)&out[obase]     = make_float4(o[0], o[1], o[2], o[3]);
  *(float4*)&out[obase + 4] = make_float4(o[4], o[5], o[6], o[7]);

  float d0 = xa.x - o[0], d1 = xa.y - o[1], d2 = xa.z - o[2], d3 = xa.w - o[3];
  float d4 = xb.x - o[4], d5 = xb.y - o[5], d6 = xb.z - o[6], d7 = xb.w - o[7];
  float part = d0 * d0 + d1 * d1 + d2 * d2 + d3 * d3
             + d4 * d4 + d5 * d5 + d6 * d6 + d7 * d7;
#pragma unroll
  for (int off = 16; off > 0; off >>= 1) part += __shfl_xor_sync(0xffffffffu, part, off);
  __shared__ float red[8];
  int lane = threadIdx.x & 31, w = threadIdx.x >> 5;
  if (lane == 0) red[w] = part;
  __syncthreads();
  if (threadIdx.x == 0) {
    float a = 0.f;
#pragma unroll
    for (int ww = 0; ww < 8; ww++) a += red[ww];
    atomicAdd(&g_loss[1], a);
  }
}

__global__ void k_total(float* __restrict__ out, int out_size) {
  if (threadIdx.x == 0 && out_size > 8388608) {
    float vq  = g_loss[0] * (1.0f / 262144.0f);   // mean over [131072, 2]
    float rec = g_loss[1] * (1.0f / 8388608.0f);  // mean over out
    out[8388608] = rec + 1.2f * vq;               // recon + codebook + 0.2*commitment
  }
}

// ---------------- launcher ----------------
extern "C" void kernel_launch(void* const* d_in, const int* in_sizes, int n_in,
                              void* d_out, int out_size) {
  const float* x    = (const float*)d_in[0];
  const float* w1   = (const float*)d_in[1];
  const float* b1   = (const float*)d_in[2];
  const float* g1   = (const float*)d_in[3];
  const float* be1  = (const float*)d_in[4];
  const float* w2   = (const float*)d_in[5];
  const float* b2   = (const float*)d_in[6];
  const float* g2   = (const float*)d_in[7];
  const float* be2  = (const float*)d_in[8];
  const float* w3   = (const float*)d_in[9];
  const float* b3   = (const float*)d_in[10];
  const float* g3   = (const float*)d_in[11];
  const float* be3  = (const float*)d_in[12];
  const float* wpre = (const float*)d_in[13];
  const float* bpre = (const float*)d_in[14];
  const float* cb   = (const float*)d_in[15];
  const float* wpost= (const float*)d_in[16];
  const float* bpost= (const float*)d_in[17];
  const float* wd1  = (const float*)d_in[18];
  const float* bd1  = (const float*)d_in[19];
  const float* g4   = (const float*)d_in[20];
  const float* be4  = (const float*)d_in[21];
  const float* wd2  = (const float*)d_in[22];
  const float* bd2  = (const float*)d_in[23];
  const float* g5   = (const float*)d_in[24];
  const float* be5  = (const float*)d_in[25];
  const float* wd3  = (const float*)d_in[26];
  const float* bd3  = (const float*)d_in[27];
  float* out = (float*)d_out;

  float *pA, *pB, *pC, *pP;
  cudaGetSymbolAddress((void**)&pA, g_A);
  cudaGetSymbolAddress((void**)&pB, g_B);
  cudaGetSymbolAddress((void**)&pC, g_C);
  cudaGetSymbolAddress((void**)&pP, g_P);

  k_zero<<<1, 256>>>();

  // encoder
  k_conv<1, 16, 256, 256, -1, 0, 4, 256, 1><<<2048, 256>>>(x, w1, b1, pA, g1, be1, 0.f);
  // conv2: oc-split x2 (PX=4 weight reuse kept; acc regs halved -> 3 blocks/SM)
  k_conv<16, 16, 128, 128, 0, 16, 4, 256, 2><<<1024, 256>>>(pA, w2, b2, pB, g1, be1,
                                                            1.f / 2097152.f);
  k_conv<16, 4, 64, 64, 16, 32, 2, 128, 1><<<512, 128>>>(pB, w3, b3, pC, g2, be2,
                                                         1.f / 524288.f);

  // VQ bottleneck (bn3 inlined + pre/vq/post fused)
  k_vq<<<512, 256>>>(pC, wpre, bpre, cb, wpost, bpost, g3, be3);

  // decoder
  k_deconv<4, 16, 128, 128, -1, 36><<<512, 256>>>(pP, wd1, bd1, pB, g3, be3, 0.f);
  k_deconv<16, 16, 256, 256, 36, 52><<<2048, 256>>>(pB, wd2, bd2, pA, g4, be4,
                                                    1.f / 524288.f);
  k_deconv3<<<4096, 256>>>(pA, wd3, bd3, x, out, g5, be5);

  k_total<<<1, 32>>>(out, out_size);
}

// round 16
// speedup vs baseline: 1.0663x; 1.0663x over previous
#include <cuda_runtime.h>

#define BN_EPS 1e-5f

// ---------------- f32x2 packed-math helpers ----------------
typedef unsigned long long u64t;

__device__ __forceinline__ u64t pk2(float lo, float hi) {
  u64t r;
  asm("mov.b64 %0, {%1, %2};" : "=l"(r)
      : "r"(__float_as_uint(lo)), "r"(__float_as_uint(hi)));
  return r;
}
__device__ __forceinline__ void fma2(u64t& d, u64t a, u64t b) {
  asm("fma.rn.f32x2 %0, %1, %2, %0;" : "+l"(d) : "l"(a), "l"(b));
}
__device__ __forceinline__ float2 upk2(u64t v) {
  unsigned lo, hi;
  asm("mov.b64 {%0, %1}, %2;" : "=r"(lo), "=r"(hi) : "l"(v));
  return make_float2(__uint_as_float(lo), __uint_as_float(hi));
}

// ---------------- scratch (device globals; no allocation allowed) ----------------
__device__ float g_A[33554432];  // 128MB: h1 [32,16,256,256] and d2 [32,16,256,256]
__device__ float g_B[8388608];   //  32MB: h2 [32,16,128,128] and d1 [32,16,128,128]
__device__ float g_C[524288];    //   2MB: h3 [32,4,64,64]
__device__ float g_P[524288];    //   2MB: post-conv [32,4,64,64]
__device__ float g_stats[136];   // [0:68) per-channel sums, [68:136) sumsqs
__device__ float g_loss[2];      // [0]=vq sq-dist sum, [1]=recon sq-err sum

// stat-set channel offsets: bn1=0(16) bn2=16(16) bn3=32(4) bn4=36(16) bn5=52(16)

__global__ void k_zero() {
  int t = threadIdx.x;
  if (t < 136) g_stats[t] = 0.f;
  if (t < 2)   g_loss[t]  = 0.f;
}

// inline BN finalize: per-block compute of scale/shift from stats (replaces k_finalize)
template <int CIN>
__device__ __forceinline__ void bn_inline(float* ssc, float* ssh, int in_off,
                                          const float* __restrict__ bng,
                                          const float* __restrict__ bnb, float binv) {
  int c = threadIdx.x;
  if (c < CIN) {
    float mean = g_stats[in_off + c] * binv;
    float var  = g_stats[68 + in_off + c] * binv - mean * mean;
    float s = bng[c] * rsqrtf(var + BN_EPS);
    ssc[c] = s;
    ssh[c] = bnb[c] - mean * s;
  }
}

// block-level per-channel sum/sumsq reduction -> global atomics (NW warps/block)
template <int NCH, int NW>
__device__ __forceinline__ void stats_reduce(float* ssum, float* ssq, int off) {
#pragma unroll
  for (int q = 0; q < NCH; q++) {
    float a = ssum[q], b = ssq[q];
#pragma unroll
    for (int o = 16; o > 0; o >>= 1) {
      a += __shfl_xor_sync(0xffffffffu, a, o);
      b += __shfl_xor_sync(0xffffffffu, b, o);
    }
    ssum[q] = a; ssq[q] = b;
  }
  __shared__ float red[2][NW][NCH];
  int lane = threadIdx.x & 31, w = threadIdx.x >> 5;
  if (lane == 0) {
#pragma unroll
    for (int q = 0; q < NCH; q++) { red[0][w][q] = ssum[q]; red[1][w][q] = ssq[q]; }
  }
  __syncthreads();
  if (threadIdx.x < NCH) {
    float a = 0.f, b = 0.f;
#pragma unroll
    for (int ww = 0; ww < NW; ww++) { a += red[0][ww][threadIdx.x]; b += red[1][ww][threadIdx.x]; }
    atomicAdd(&g_stats[off + threadIdx.x], a);
    atomicAdd(&g_stats[68 + off + threadIdx.x], b);
  }
}

// ---------------- conv k=4 s=2 p=1 (r10 body; BN finalize inlined) ----------------
template <int CIN, int COUT, int HOUT, int WOUT, int IN_OFF, int OUT_OFF, int PX, int BD>
__global__ void __launch_bounds__(BD, (BD == 128) ? 5 : 2)
k_conv(const float* __restrict__ in, const float* __restrict__ wgt,
       const float* __restrict__ bias, float* __restrict__ out,
       const float* __restrict__ bng, const float* __restrict__ bnb, float binv) {
  constexpr int HIN = 2 * HOUT, WIN = 2 * WOUT;
  constexpr int NJ = COUT / 2;
  constexpr int NV = 2 * PX + 2;
  __shared__ __align__(16) float sw[16 * CIN * COUT];
  __shared__ float ssc[CIN], ssh[CIN];
  for (int i = threadIdx.x; i < 16 * CIN * COUT; i += blockDim.x) {
    int tap = i / (CIN * COUT);
    int r = i - tap * CIN * COUT;
    int ic = r / COUT, oc = r - ic * COUT;
    sw[i] = wgt[(oc * CIN + ic) * 16 + tap];
  }
  if (IN_OFF >= 0) bn_inline<CIN>(ssc, ssh, IN_OFF, bng, bnb, binv);
  __syncthreads();

  int gtid = blockIdx.x * blockDim.x + threadIdx.x;
  int base = gtid * PX;
  int ox0 = base % WOUT;  // multiple of PX
  int t2  = base / WOUT;
  int oy  = t2 % HOUT;
  int b   = t2 / HOUT;

  int ox2 = 2 * ox0 - 1;  // vr[m] = in_row[ox2 + m], m = 0..NV-1
  bool interior = (ox0 > 0) && (ox0 < WOUT - PX);

  u64t acc2[PX][NJ];
#pragma unroll
  for (int j = 0; j < NJ; j++) {
    u64t bb = pk2(bias[2 * j], bias[2 * j + 1]);
#pragma unroll
    for (int p = 0; p < PX; p++) acc2[p][j] = bb;
  }

#pragma unroll 1
  for (int ky = 0; ky < 4; ky++) {
    int iy = 2 * oy - 1 + ky;
    if ((unsigned)iy >= (unsigned)HIN) continue;
#pragma unroll 1
    for (int ic = 0; ic < CIN; ic++) {
      int rowoff = ((b * CIN + ic) * HIN + iy) * WIN;
      float vr[NV];
      if (interior) {
        const float4* r4 = (const float4*)(in + rowoff + 2 * ox0 - 4);  // 16B aligned
        float4 a = r4[0], c = r4[1];
        vr[0] = a.w;
        vr[1] = c.x; vr[2] = c.y; vr[3] = c.z; vr[4] = c.w;
        if (PX == 2) {
          vr[5] = in[rowoff + 2 * ox0 + 4];
        } else {
          float4 d = r4[2];
          vr[5] = d.x; vr[6] = d.y; vr[7] = d.z; vr[8] = d.w;
          vr[9] = in[rowoff + 2 * ox0 + 8];
        }
        if (IN_OFF >= 0) {
          float sc = ssc[ic], sh = ssh[ic];
#pragma unroll
          for (int m = 0; m < NV; m++) vr[m] = fmaxf(fmaf(vr[m], sc, sh), 0.f);
        }
      } else {
        float sc = (IN_OFF >= 0) ? ssc[ic] : 0.f;
        float sh = (IN_OFF >= 0) ? ssh[ic] : 0.f;
#pragma unroll
        for (int m = 0; m < NV; m++) {
          int ix = ox2 + m;
          float t = 0.f;
          if ((unsigned)ix < (unsigned)WIN) {
            t = in[rowoff + ix];
            if (IN_OFF >= 0) t = fmaxf(fmaf(t, sc, sh), 0.f);
          }
          vr[m] = t;  // pad stays exactly 0
        }
      }

      u64t vv[NV];
#pragma unroll
      for (int m = 0; m < NV; m++) vv[m] = pk2(vr[m], vr[m]);

      const u64t* wtap = (const u64t*)&sw[(ky * 4 * CIN + ic) * COUT];
#pragma unroll
      for (int kx = 0; kx < 4; kx++) {
        const u64t* wrow2 = wtap + kx * (CIN * NJ);
#pragma unroll
        for (int j = 0; j < NJ; j++) {
          u64t w2 = wrow2[j];
#pragma unroll
          for (int p = 0; p < PX; p++) fma2(acc2[p][j], vv[kx + 2 * p], w2);
        }
      }
    }
  }

  float ssum[COUT], ssq[COUT];
#pragma unroll
  for (int j = 0; j < NJ; j++) {
    int oc0 = 2 * j;
    float oa[PX], ob[PX];
#pragma unroll
    for (int p = 0; p < PX; p++) {
      float2 pr = upk2(acc2[p][j]);
      oa[p] = pr.x; ob[p] = pr.y;
    }
    if (PX == 4) {
      *(float4*)&out[((b * COUT + oc0) * HOUT + oy) * WOUT + ox0] =
          make_float4(oa[0], oa[1], oa[2], oa[3]);
      *(float4*)&out[((b * COUT + oc0 + 1) * HOUT + oy) * WOUT + ox0] =
          make_float4(ob[0], ob[1], ob[2], ob[3]);
    } else {
      *(float2*)&out[((b * COUT + oc0) * HOUT + oy) * WOUT + ox0] =
          make_float2(oa[0], oa[1]);
      *(float2*)&out[((b * COUT + oc0 + 1) * HOUT + oy) * WOUT + ox0] =
          make_float2(ob[0], ob[1]);
    }
    float sa = 0.f, qa = 0.f, sb = 0.f, qb = 0.f;
#pragma unroll
    for (int p = 0; p < PX; p++) {
      sa += oa[p]; qa += oa[p] * oa[p];
      sb += ob[p]; qb += ob[p] * ob[p];
    }
    ssum[oc0] = sa; ssq[oc0] = qa;
    ssum[oc0 + 1] = sb; ssq[oc0 + 1] = qb;
  }
  stats_reduce<COUT, BD / 32>(ssum, ssq, OUT_OFF);
}

// ---------------- conv-transpose k=4 s=2 p=1 (r10 body; BN finalize inlined) ----------------
template <int CIN, int COUT, int HOUT, int WOUT, int IN_OFF, int OUT_OFF>
__global__ void __launch_bounds__(256, 2)
k_deconv(const float* __restrict__ in, const float* __restrict__ wgt,
         const float* __restrict__ bias, float* __restrict__ out,
         const float* __restrict__ bng, const float* __restrict__ bnb, float binv) {
  constexpr int HIN = HOUT / 2, WIN = WOUT / 2;
  constexpr int NJ = COUT / 2;
  __shared__ __align__(16) float sw[16 * CIN * COUT];
  __shared__ float ssc[CIN], ssh[CIN];
  for (int i = threadIdx.x; i < 16 * CIN * COUT; i += blockDim.x) {
    int tap = i / (CIN * COUT);
    int r = i - tap * CIN * COUT;
    int ic = r / COUT, oc = r - ic * COUT;
    sw[i] = wgt[(ic * COUT + oc) * 16 + tap];
  }
  if (IN_OFF >= 0) bn_inline<CIN>(ssc, ssh, IN_OFF, bng, bnb, binv);
  __syncthreads();

  int gtid = blockIdx.x * blockDim.x + threadIdx.x;
  int base = gtid * 4;
  int ox0 = base % WOUT;  // multiple of 4
  int t2  = base / WOUT;
  int oy  = t2 % HOUT;
  int b   = t2 / HOUT;

  int ry  = (oy + 1) & 1;        // valid ky in {ry, ry+2}
  int iy0 = (oy + 1 - ry) >> 1;  // iy for ky=ry; ky=ry+2 -> iy0-1
  int ixb = (ox0 >> 1) - 1;      // vr[m] = row[ixb+m], m 0..3

  u64t acc2[4][NJ];
#pragma unroll
  for (int j = 0; j < NJ; j++) {
    u64t bb = pk2(bias[2 * j], bias[2 * j + 1]);
#pragma unroll
    for (int p = 0; p < 4; p++) acc2[p][j] = bb;
  }

#pragma unroll 1
  for (int ty = 0; ty < 2; ty++) {
    int iy = iy0 - ty;
    if ((unsigned)iy >= (unsigned)HIN) continue;
    int ky = ry + 2 * ty;
#pragma unroll 2
    for (int ic = 0; ic < CIN; ic++) {
      int rowoff = ((b * CIN + ic) * HIN + iy) * WIN;
      float sc = (IN_OFF >= 0) ? ssc[ic] : 0.f;
      float sh = (IN_OFF >= 0) ? ssh[ic] : 0.f;
      float vr[4];
#pragma unroll
      for (int m = 0; m < 4; m++) {
        int ix = ixb + m;
        float t = 0.f;
        if ((unsigned)ix < (unsigned)WIN) {
          t = in[rowoff + ix];
          if (IN_OFF >= 0) t = fmaxf(fmaf(t, sc, sh), 0.f);
        }
        vr[m] = t;  // pad stays exactly 0
      }
      u64t vv[4];
#pragma unroll
      for (int m = 0; m < 4; m++) vv[m] = pk2(vr[m], vr[m]);

#pragma unroll
      for (int pc = 0; pc < 2; pc++) {
        int rx = (pc + 1) & 1;
#pragma unroll
        for (int tx = 0; tx < 2; tx++) {
          int kx = rx + 2 * tx;
          int m0 = pc + 1 - tx;  // pixel pc; pixel pc+2 uses m0+1
          const u64t* wrow2 = (const u64t*)&sw[((ky * 4 + kx) * CIN + ic) * COUT];
#pragma unroll
          for (int j = 0; j < NJ; j++) {
            u64t w2 = wrow2[j];
            fma2(acc2[pc][j],     vv[m0],     w2);
            fma2(acc2[pc + 2][j], vv[m0 + 1], w2);
          }
        }
      }
    }
  }

  float ssum[COUT], ssq[COUT];
#pragma unroll
  for (int j = 0; j < NJ; j++) {
    float2 p0 = upk2(acc2[0][j]), p1 = upk2(acc2[1][j]);
    float2 p2 = upk2(acc2[2][j]), p3 = upk2(acc2[3][j]);
    float4 oa = make_float4(p0.x, p1.x, p2.x, p3.x);
    float4 ob = make_float4(p0.y, p1.y, p2.y, p3.y);
    int oc0 = 2 * j;
    *(float4*)&out[((b * COUT + oc0) * HOUT + oy) * WOUT + ox0] = oa;
    *(float4*)&out[((b * COUT + oc0 + 1) * HOUT + oy) * WOUT + ox0] = ob;
    ssum[oc0]     = oa.x + oa.y + oa.z + oa.w;
    ssq[oc0]      = oa.x * oa.x + oa.y * oa.y + oa.z * oa.z + oa.w * oa.w;
    ssum[oc0 + 1] = ob.x + ob.y + ob.z + ob.w;
    ssq[oc0 + 1]  = ob.x * ob.x + ob.y * ob.y + ob.z * ob.z + ob.w * ob.w;
  }
  stats_reduce<COUT, 8>(ssum, ssq, OUT_OFF);
}

// ---------------- fused: bn3+relu -> 1x1 pre-conv -> VQ -> 1x1 post-conv ----------------
__global__ void k_vq(const float* __restrict__ C, const float* __restrict__ wpre,
                     const float* __restrict__ bpre, const float* __restrict__ cb,
                     const float* __restrict__ wpost, const float* __restrict__ bpost,
                     const float* __restrict__ g3, const float* __restrict__ be3) {
  __shared__ float scb[512];
  __shared__ float ssc[4], ssh[4];
  for (int i = threadIdx.x; i < 512; i += blockDim.x) scb[i] = cb[i];
  bn_inline<4>(ssc, ssh, 32, g3, be3, 1.f / 131072.f);
  __syncthreads();

  int t  = blockIdx.x * blockDim.x + threadIdx.x;  // 131072 pixels
  int sp = t & 4095;
  int b  = t >> 12;

  float h[4];
#pragma unroll
  for (int ic = 0; ic < 4; ic++) {
    float raw = C[((b * 4 + ic) << 12) + sp];
    h[ic] = fmaxf(fmaf(raw, ssc[ic], ssh[ic]), 0.f);
  }
  float q0 = bpre[0], q1 = bpre[1];
#pragma unroll
  for (int ic = 0; ic < 4; ic++) {
    q0 = fmaf(h[ic], wpre[ic], q0);
    q1 = fmaf(h[ic], wpre[4 + ic], q1);
  }

  float best = 3.4e38f;
  int bi = 0;
  const float2* cb2 = (const float2*)scb;
#pragma unroll 8
  for (int j = 0; j < 256; j++) {
    float2 c = cb2[j];
    float d0 = q0 - c.x, d1 = q1 - c.y;
    float d = d0 * d0 + d1 * d1;
    if (d < best) { best = d; bi = j; }  // first-min tie-break == jnp.argmin
  }
  float c0 = scb[2 * bi], c1 = scb[2 * bi + 1];

#pragma unroll
  for (int j = 0; j < 4; j++) {
    float pv = bpost[j] + wpost[2 * j] * c0 + wpost[2 * j + 1] * c1;
    g_P[((b * 4 + j) << 12) + sp] = pv;
  }

  float part = best;
#pragma unroll
  for (int o = 16; o > 0; o >>= 1) part += __shfl_xor_sync(0xffffffffu, part, o);
  __shared__ float red[8];
  int lane = threadIdx.x & 31, w = threadIdx.x >> 5;
  if (lane == 0) red[w] = part;
  __syncthreads();
  if (threadIdx.x == 0) {
    float a = 0.f;
#pragma unroll
    for (int ww = 0; ww < 8; ww++) a += red[ww];
    atomicAdd(&g_loss[0], a);
  }
}

// ---------------- final deconv (16->1) + sigmoid + recon loss (r10 body; BN inlined) ----------------
__global__ void __launch_bounds__(256, 2)
k_deconv3(const float* __restrict__ in, const float* __restrict__ wgt,
          const float* __restrict__ bias, const float* __restrict__ x,
          float* __restrict__ out,
          const float* __restrict__ g5, const float* __restrict__ be5) {
  constexpr int CIN = 16, HIN = 256, WIN = 256;
  __shared__ __align__(16) u64t swd[256];  // swd[tap*16+ic] = {w, w}
  __shared__ float ssc[16], ssh[16];
  if (threadIdx.x < 256) {
    int tap = threadIdx.x >> 4, ic = threadIdx.x & 15;
    float w = wgt[ic * 16 + tap];
    swd[threadIdx.x] = pk2(w, w);
  }
  bn_inline<16>(ssc, ssh, 52, g5, be5, 1.f / 2097152.f);
  __syncthreads();

  int gtid = blockIdx.x * blockDim.x + threadIdx.x;
  int base = gtid * 8;
  int ox0 = base & 511;
  int t2  = base >> 9;
  int oy  = t2 & 511;
  int b   = t2 >> 9;

  int ry  = (oy + 1) & 1;
  int iy0 = (oy + 1 - ry) >> 1;
  int ixb = (ox0 >> 1) - 1;  // vr[m] = row[ixb+m], m 0..5
  bool interior = (ox0 > 0) && (ox0 < 504);

  float bb = bias[0];
  u64t acc2[4];
#pragma unroll
  for (int s = 0; s < 4; s++) acc2[s] = pk2(bb, bb);

#pragma unroll 1
  for (int ty = 0; ty < 2; ty++) {
    int iy = iy0 - ty;
    if ((unsigned)iy >= (unsigned)HIN) continue;
    int ky = ry + 2 * ty;
#pragma unroll 1
    for (int ic = 0; ic < CIN; ic++) {
      int rowoff = ((b * CIN + ic) * HIN + iy) * WIN;
      float sc = ssc[ic], sh = ssh[ic];
      float vr[6];
      if (interior) {
        // ixb+1 = ox0/2, multiple of 4 -> 16B-aligned float4 covers vr[1..4]
        float v0 = in[rowoff + ixb];
        float4 c4 = *(const float4*)(in + rowoff + ixb + 1);
        float v5 = in[rowoff + ixb + 5];
        vr[0] = fmaxf(fmaf(v0,   sc, sh), 0.f);
        vr[1] = fmaxf(fmaf(c4.x, sc, sh), 0.f);
        vr[2] = fmaxf(fmaf(c4.y, sc, sh), 0.f);
        vr[3] = fmaxf(fmaf(c4.z, sc, sh), 0.f);
        vr[4] = fmaxf(fmaf(c4.w, sc, sh), 0.f);
        vr[5] = fmaxf(fmaf(v5,   sc, sh), 0.f);
      } else {
#pragma unroll
        for (int m = 0; m < 6; m++) {
          int ix = ixb + m;
          float t = 0.f;
          if ((unsigned)ix < (unsigned)WIN)
            t = fmaxf(fmaf(in[rowoff + ix], sc, sh), 0.f);
          vr[m] = t;  // pad stays exactly 0
        }
      }
      u64t vp[4];
#pragma unroll
      for (int m = 0; m < 4; m++) vp[m] = pk2(vr[m], vr[m + 2]);

#pragma unroll
      for (int pc = 0; pc < 2; pc++) {
        int rx = (pc + 1) & 1;
#pragma unroll
        for (int tx = 0; tx < 2; tx++) {
          int kx = rx + 2 * tx;
          u64t wd = swd[(ky * 4 + kx) * 16 + ic];
          int m0 = pc + 1 - tx;
          fma2(acc2[pc],     vp[m0],     wd);
          fma2(acc2[pc + 2], vp[m0 + 1], wd);
        }
      }
    }
  }

  float o[8];
#pragma unroll
  for (int s = 0; s < 4; s++) {
    float2 pr = upk2(acc2[s]);
    o[s]     = 1.f / (1.f + __expf(-pr.x));
    o[s + 4] = 1.f / (1.f + __expf(-pr.y));
  }

  int obase = (b * 512 + oy) * 512 + ox0;
  float4 xa = *(const float4*)&x[obase];
  float4 xb = *(const float4*)&x[obase + 4];
  *(float4*)&out[obase]     = make_float4(o[0], o[1], o[2], o[3]);
  *(float4*)&out[obase + 4] = make_float4(o[4], o[5], o[6], o[7]);

  float d0 = xa.x - o[0], d1 = xa.y - o[1], d2 = xa.z - o[2], d3 = xa.w - o[3];
  float d4 = xb.x - o[4], d5 = xb.y - o[5], d6 = xb.z - o[6], d7 = xb.w - o[7];
  float part = d0 * d0 + d1 * d1 + d2 * d2 + d3 * d3
             + d4 * d4 + d5 * d5 + d6 * d6 + d7 * d7;
#pragma unroll
  for (int off = 16; off > 0; off >>= 1) part += __shfl_xor_sync(0xffffffffu, part, off);
  __shared__ float red[8];
  int lane = threadIdx.x & 31, w = threadIdx.x >> 5;
  if (lane == 0) red[w] = part;
  __syncthreads();
  if (threadIdx.x == 0) {
    float a = 0.f;
#pragma unroll
    for (int ww = 0; ww < 8; ww++) a += red[ww];
    atomicAdd(&g_loss[1], a);
  }
}

__global__ void k_total(float* __restrict__ out, int out_size) {
  if (threadIdx.x == 0 && out_size > 8388608) {
    float vq  = g_loss[0] * (1.0f / 262144.0f);   // mean over [131072, 2]
    float rec = g_loss[1] * (1.0f / 8388608.0f);  // mean over out
    out[8388608] = rec + 1.2f * vq;               // recon + codebook + 0.2*commitment
  }
}

// ---------------- launcher ----------------
extern "C" void kernel_launch(void* const* d_in, const int* in_sizes, int n_in,
                              void* d_out, int out_size) {
  const float* x    = (const float*)d_in[0];
  const float* w1   = (const float*)d_in[1];
  const float* b1   = (const float*)d_in[2];
  const float* g1   = (const float*)d_in[3];
  const float* be1  = (const float*)d_in[4];
  const float* w2   = (const float*)d_in[5];
  const float* b2   = (const float*)d_in[6];
  const float* g2   = (const float*)d_in[7];
  const float* be2  = (const float*)d_in[8];
  const float* w3   = (const float*)d_in[9];
  const float* b3   = (const float*)d_in[10];
  const float* g3   = (const float*)d_in[11];
  const float* be3  = (const float*)d_in[12];
  const float* wpre = (const float*)d_in[13];
  const float* bpre = (const float*)d_in[14];
  const float* cb   = (const float*)d_in[15];
  const float* wpost= (const float*)d_in[16];
  const float* bpost= (const float*)d_in[17];
  const float* wd1  = (const float*)d_in[18];
  const float* bd1  = (const float*)d_in[19];
  const float* g4   = (const float*)d_in[20];
  const float* be4  = (const float*)d_in[21];
  const float* wd2  = (const float*)d_in[22];
  const float* bd2  = (const float*)d_in[23];
  const float* g5   = (const float*)d_in[24];
  const float* be5  = (const float*)d_in[25];
  const float* wd3  = (const float*)d_in[26];
  const float* bd3  = (const float*)d_in[27];
  float* out = (float*)d_out;

  float *pA, *pB, *pC, *pP;
  cudaGetSymbolAddress((void**)&pA, g_A);
  cudaGetSymbolAddress((void**)&pB, g_B);
  cudaGetSymbolAddress((void**)&pC, g_C);
  cudaGetSymbolAddress((void**)&pP, g_P);

  k_zero<<<1, 256>>>();

  // encoder (BN finalize inlined into consumers)
  k_conv<1, 16, 256, 256, -1, 0, 4, 256><<<2048, 256>>>(x, w1, b1, pA, g1, be1, 0.f);
  k_conv<16, 16, 128, 128, 0, 16, 4, 256><<<512, 256>>>(pA, w2, b2, pB, g1, be1, 1.f / 2097152.f);
  k_conv<16, 4, 64, 64, 16, 32, 2, 128><<<512, 128>>>(pB, w3, b3, pC, g2, be2, 1.f / 524288.f);

  // VQ bottleneck (bn3 inlined + pre/vq/post fused)
  k_vq<<<512, 256>>>(pC, wpre, bpre, cb, wpost, bpost, g3, be3);

  // decoder
  k_deconv<4, 16, 128, 128, -1, 36><<<512, 256>>>(pP, wd1, bd1, pB, g3, be3, 0.f);
  k_deconv<16, 16, 256, 256, 36, 52><<<2048, 256>>>(pB, wd2, bd2, pA, g4, be4, 1.f / 524288.f);
  k_deconv3<<<4096, 256>>>(pA, wd3, bd3, x, out, g5, be5);

  k_total<<<1, 32>>>(out, out_size);
}